// round 17
// baseline (speedup 1.0000x reference)
#include <cuda_runtime.h>
#include <cuda_bf16.h>
#include <math.h>
#include <stdint.h>
#include <float.h>

// Problem constants
#define NA 16
#define NS 64
#define NB 100
#define NE 12
#define MAXLEN 20
#define DD 512
#define NCOL (NA*NE)          // 192
#define NGRP (NA*NS)          // 1024
#define NROW (NGRP*NB)        // 102400
#define EPSF 1e-5f
#define DELTA_F 0.2f

// Output layout (float32, concatenated flattened in return order)
#define OUT_DIND 0
#define OUT_DSIM (NGRP*NCOL)            // 196608
#define OUT_MARGIN (2*NGRP*NCOL)        // 393216
#define OUT_DTI (2*NGRP*NCOL + 1)       // 393217
#define N_DTI (NA*NS*NB*MAXLEN)         // 2048000

// ---------------- device scratch (no allocs allowed) ----------------
__device__ float g_S[(size_t)NROW * NCOL];     // 78.6 MB
__device__ float g_Dsim[NGRP * NCOL];
__device__ int   g_Dind[NGRP * NCOL];
__device__ float g_vis_sum[NCOL];
__device__ int   g_vis_cnt[NCOL];
__device__ float g_Sf[NA * NS * NA];

// ---------------- helpers ----------------
__device__ __forceinline__ float warpSum(float v) {
#pragma unroll
    for (int o = 16; o > 0; o >>= 1) v += __shfl_down_sync(0xffffffffu, v, o);
    return v;
}
__device__ float blockSum(float v, float* sh) {
    __syncthreads();
    int lane = threadIdx.x & 31, w = threadIdx.x >> 5;
    v = warpSum(v);
    if (lane == 0) sh[w] = v;
    __syncthreads();
    int nw = (blockDim.x + 31) >> 5;
    if (w == 0) {
        float r = (lane < nw) ? sh[lane] : 0.f;
        r = warpSum(r);
        if (lane == 0) sh[0] = r;
    }
    __syncthreads();
    return sh[0];
}

__device__ __forceinline__ uint32_t smem_u32(const void* p) {
    uint32_t a;
    asm("{ .reg .u64 t; cvta.to.shared.u64 t, %1; cvt.u32.u64 %0, t; }" : "=r"(a) : "l"(p));
    return a;
}

// ---------------- GEMM: mma.sync bf16 3-split (base ISA, runs on sm_103) ----
// S[m][c] = sum_k vis[m,k]*word[c,k].  CTA: M=128, N=192 (all cols), K=512 in
// 16 chunks of 32.  8 warps (2x4), warp tile 64x48 = 24 m16n8k16 atoms.
// Split: a = ah + al (bf16 hi/lo); ab ~= ah*bh + ah*bl + al*bh, fp32 accum.
#define CHUNK 32
#define NCHUNKS (DD / CHUNK)       // 16
// smem: bf16 rows of 16 k-elems padded to 24 (48B) -> conflict-free ldmatrix
#define A_SL 6144                  // 128 rows * 48B, per k16-slice
#define B_SL 9216                  // 192 rows * 48B
#define SM_AH 0
#define SM_AL (2*A_SL)             // 12288
#define SM_BH (4*A_SL)             // 24576
#define SM_BL (SM_BH + 2*B_SL)     // 43008
#define GEMM_SMEM (SM_BL + 2*B_SL) // 61440

__device__ __forceinline__ uint32_t pack_bf2(float x, float y) {
    __nv_bfloat16 bx = __float2bfloat16(x), by = __float2bfloat16(y);
    return (uint32_t)__bfloat16_as_ushort(bx) | ((uint32_t)__bfloat16_as_ushort(by) << 16);
}
// split one float4 into hi/lo packed pairs
__device__ __forceinline__ void split4(float4 f, uint32_t& h0, uint32_t& h1,
                                       uint32_t& l0, uint32_t& l1) {
    __nv_bfloat16 hx = __float2bfloat16(f.x), hy = __float2bfloat16(f.y);
    __nv_bfloat16 hz = __float2bfloat16(f.z), hw = __float2bfloat16(f.w);
    float rx = f.x - __bfloat162float(hx), ry = f.y - __bfloat162float(hy);
    float rz = f.z - __bfloat162float(hz), rw = f.w - __bfloat162float(hw);
    h0 = (uint32_t)__bfloat16_as_ushort(hx) | ((uint32_t)__bfloat16_as_ushort(hy) << 16);
    h1 = (uint32_t)__bfloat16_as_ushort(hz) | ((uint32_t)__bfloat16_as_ushort(hw) << 16);
    l0 = pack_bf2(rx, ry);
    l1 = pack_bf2(rz, rw);
}
__device__ __forceinline__ void sts_v4(uint32_t addr, uint32_t a, uint32_t b,
                                       uint32_t c, uint32_t d) {
    asm volatile("st.shared.v4.b32 [%0], {%1, %2, %3, %4};"
                 :: "r"(addr), "r"(a), "r"(b), "r"(c), "r"(d) : "memory");
}
__device__ __forceinline__ void ldm_x4(uint32_t* r, uint32_t addr) {
    asm volatile("ldmatrix.sync.aligned.m8n8.x4.shared.b16 {%0,%1,%2,%3}, [%4];"
                 : "=r"(r[0]), "=r"(r[1]), "=r"(r[2]), "=r"(r[3]) : "r"(addr));
}
__device__ __forceinline__ void ldm_x2(uint32_t* r, uint32_t addr) {
    asm volatile("ldmatrix.sync.aligned.m8n8.x2.shared.b16 {%0,%1}, [%2];"
                 : "=r"(r[0]), "=r"(r[1]) : "r"(addr));
}
__device__ __forceinline__ void mma_bf16(float* c, const uint32_t* a, const uint32_t* b) {
    asm volatile(
        "mma.sync.aligned.m16n8k16.row.col.f32.bf16.bf16.f32 "
        "{%0,%1,%2,%3}, {%4,%5,%6,%7}, {%8,%9}, {%0,%1,%2,%3};"
        : "+f"(c[0]), "+f"(c[1]), "+f"(c[2]), "+f"(c[3])
        : "r"(a[0]), "r"(a[1]), "r"(a[2]), "r"(a[3]), "r"(b[0]), "r"(b[1]));
}

__global__ void __launch_bounds__(256, 1) gemm_kernel(const float* __restrict__ vis,
                                                      const float* __restrict__ word) {
    extern __shared__ char smem[];
    uint32_t sb = smem_u32(smem);
    int t = threadIdx.x;
    int m_base = blockIdx.x * 128;
    int lane = t & 31, wid = t >> 5;
    int wm = wid >> 2, wn = wid & 3;           // warp tile: rows wm*64, cols wn*48

    // ---- staging pointers ----
    // A: thread t handles (row = t>>1, slice = t&1): 4 float4 per chunk
    const float4* Ag = (const float4*)(vis + (size_t)(m_base + (t >> 1)) * DD) + (t & 1) * 4;
    // B: unit u = (row = u>>1, slice = u&1); thread t does u=t, and u=256+t if t<128
    const float4* Bg1 = (const float4*)(word + (size_t)(t >> 1) * DD) + (t & 1) * 4;
    bool hasB2 = t < 128;
    const float4* Bg2 = (const float4*)(word + (size_t)(128 + (t >> 1)) * DD) + (t & 1) * 4;

    // STS destinations (hi base; lo base = +A/B lo offset)
    uint32_t a_dst = sb + SM_AH + (uint32_t)(t & 1) * A_SL + (uint32_t)(t >> 1) * 48;
    uint32_t b_dst1 = sb + SM_BH + (uint32_t)(t & 1) * B_SL + (uint32_t)(t >> 1) * 48;
    uint32_t b_dst2 = sb + SM_BH + (uint32_t)(t & 1) * B_SL + (uint32_t)(128 + (t >> 1)) * 48;

    float acc[96];
#pragma unroll
    for (int i = 0; i < 96; i++) acc[i] = 0.f;

    // ldmatrix source addresses (per slice s add s*A_SL / s*B_SL)
    // A atom im: rows wm*64+im*16, q = lane>>3: row += (q&1)*8 + (lane&7), koff = (q>>1)*16
    uint32_t a_ld_base = sb + SM_AH +
        (uint32_t)(wm * 64 + (lane & 7) + ((lane >> 3) & 1) * 8) * 48 +
        (uint32_t)((lane >> 4) & 1) * 16;
    // B atom in: rows wn*48+in*8, x2 uses lane&15: row += (lane&7), koff = ((lane&15)>>3)*16
    uint32_t b_ld_base = sb + SM_BH +
        (uint32_t)(wn * 48 + (lane & 7)) * 48 +
        (uint32_t)(((lane & 15) >> 3)) * 16;

    float4 ra[4], rb1[4], rb2[4];
#pragma unroll
    for (int i = 0; i < 4; i++) {
        ra[i] = Ag[i];
        rb1[i] = Bg1[i];
        if (hasB2) rb2[i] = Bg2[i];
    }

    for (int c = 0; c < NCHUNKS; c++) {
        // ---- STS staged chunk (split hi/lo) ----
        {
            uint32_t h0, h1, h2, h3, l0, l1, l2, l3;
            split4(ra[0], h0, h1, l0, l1); split4(ra[1], h2, h3, l2, l3);
            sts_v4(a_dst, h0, h1, h2, h3);
            sts_v4(a_dst + (SM_AL - SM_AH), l0, l1, l2, l3);
            split4(ra[2], h0, h1, l0, l1); split4(ra[3], h2, h3, l2, l3);
            sts_v4(a_dst + 16, h0, h1, h2, h3);
            sts_v4(a_dst + 16 + (SM_AL - SM_AH), l0, l1, l2, l3);

            split4(rb1[0], h0, h1, l0, l1); split4(rb1[1], h2, h3, l2, l3);
            sts_v4(b_dst1, h0, h1, h2, h3);
            sts_v4(b_dst1 + (SM_BL - SM_BH), l0, l1, l2, l3);
            split4(rb1[2], h0, h1, l0, l1); split4(rb1[3], h2, h3, l2, l3);
            sts_v4(b_dst1 + 16, h0, h1, h2, h3);
            sts_v4(b_dst1 + 16 + (SM_BL - SM_BH), l0, l1, l2, l3);
            if (hasB2) {
                split4(rb2[0], h0, h1, l0, l1); split4(rb2[1], h2, h3, l2, l3);
                sts_v4(b_dst2, h0, h1, h2, h3);
                sts_v4(b_dst2 + (SM_BL - SM_BH), l0, l1, l2, l3);
                split4(rb2[2], h0, h1, l0, l1); split4(rb2[3], h2, h3, l2, l3);
                sts_v4(b_dst2 + 16, h0, h1, h2, h3);
                sts_v4(b_dst2 + 16 + (SM_BL - SM_BH), l0, l1, l2, l3);
            }
        }
        __syncthreads();

        // ---- prefetch next chunk while tensor cores work ----
        if (c + 1 < NCHUNKS) {
            int o = (c + 1) * 8;
#pragma unroll
            for (int i = 0; i < 4; i++) {
                ra[i] = Ag[o + i];
                rb1[i] = Bg1[o + i];
                if (hasB2) rb2[i] = Bg2[o + i];
            }
        }

        // ---- consume: 2 k16 slices, 3 split combos each ----
#pragma unroll
        for (int s = 0; s < 2; s++) {
            uint32_t ah[4][4], al[4][4], bh[6][2], bl[6][2];
#pragma unroll
            for (int im = 0; im < 4; im++) {
                uint32_t ad = a_ld_base + (uint32_t)s * A_SL + (uint32_t)(im * 16) * 48;
                ldm_x4(ah[im], ad);
                ldm_x4(al[im], ad + (SM_AL - SM_AH));
            }
#pragma unroll
            for (int in = 0; in < 6; in++) {
                uint32_t bd = b_ld_base + (uint32_t)s * B_SL + (uint32_t)(in * 8) * 48;
                ldm_x2(bh[in], bd);
                ldm_x2(bl[in], bd + (SM_BL - SM_BH));
            }
#pragma unroll
            for (int im = 0; im < 4; im++) {
#pragma unroll
                for (int in = 0; in < 6; in++) {
                    float* cc = &acc[(im * 6 + in) * 4];
                    mma_bf16(cc, ah[im], bh[in]);
                    mma_bf16(cc, ah[im], bl[in]);
                    mma_bf16(cc, al[im], bh[in]);
                }
            }
        }
        __syncthreads();
    }

    // ---- epilogue: write 64x48 warp tile to g_S ----
    int g = lane >> 2, tq = lane & 3;
#pragma unroll
    for (int im = 0; im < 4; im++) {
#pragma unroll
        for (int in = 0; in < 6; in++) {
            const float* cc = &acc[(im * 6 + in) * 4];
            int mr = m_base + wm * 64 + im * 16 + g;
            int col = wn * 48 + in * 8 + 2 * tq;
            float2 v01 = make_float2(cc[0], cc[1]);
            float2 v23 = make_float2(cc[2], cc[3]);
            *(float2*)(g_S + (size_t)mr * NCOL + col) = v01;
            *(float2*)(g_S + (size_t)(mr + 8) * NCOL + col) = v23;
        }
    }
}

// ---------------- exact fp32 dot (fixup path) ----------------
__device__ float dotExact(const float* __restrict__ a, const float* __restrict__ b) {
    float s = 0.f;
#pragma unroll 8
    for (int i = 0; i < DD / 4; i++) {
        float4 x = __ldg((const float4*)a + i);
        float4 y = __ldg((const float4*)b + i);
        s += x.x * y.x + x.y * y.y + x.z * y.z + x.w * y.w;
    }
    return s;
}

// ---------------- kernel 2: max/argmax over Nb + exact rescue ----------------
__global__ void maxred_kernel(const int* __restrict__ elen,
                              const float* __restrict__ vis,
                              const float* __restrict__ word,
                              float* __restrict__ out) {
    int g = blockIdx.x;        // a*NS + s
    int c = threadIdx.x;       // 0..191
    int aw = c / NE, e = c - aw * NE;
    float best = 0.f;
    int bi = 0;
    if (e < elen[aw]) {
        const float* p = g_S + (size_t)g * NB * NCOL + c;
        best = -FLT_MAX;
        for (int b = 0; b < NB; b++) {
            float v = p[(size_t)b * NCOL];
            if (v > best) { best = v; bi = b; }
        }
        // exact rescue: any TC score within tau of TC max gets an exact fp32 dot
        const float tau = 0.02f;
        int ncand = 0;
        for (int b = 0; b < NB; b++)
            if (p[(size_t)b * NCOL] > best - tau) ncand++;
        if (ncand > 1) {
            float bestEx = -FLT_MAX, bestTc = best;
            int bEx = 0;
            for (int b = 0; b < NB; b++) {
                float v = p[(size_t)b * NCOL];
                if (v > best - tau) {
                    float ex = dotExact(vis + ((size_t)g * NB + b) * DD,
                                        word + (size_t)c * DD);
                    if (ex > bestEx) { bestEx = ex; bEx = b; bestTc = v; }
                }
            }
            bi = bEx; best = bestTc;
        }
    }
    int idx = g * NCOL + c;
    out[OUT_DIND + idx] = (float)bi;
    out[OUT_DSIM + idx] = best;
    g_Dsim[idx] = best;
    g_Dind[idx] = bi;
}

// ---------------- kernel 3: IoU d_ti_n ----------------
__global__ void iou_kernel(const float* __restrict__ boxes,
                           const float* __restrict__ dets,
                           float* __restrict__ out) {
    int idx = blockIdx.x * blockDim.x + threadIdx.x;
    if (idx >= N_DTI) return;
    int m = idx % MAXLEN;
    int rest = idx / MAXLEN;
    int a = rest / (NS * NB);
    const float* A = boxes + (size_t)rest * 4;
    const float* B = dets + (size_t)(a * MAXLEN + m) * 4;
    float ax0 = A[0], ay0 = A[1], ax1 = A[2], ay1 = A[3];
    float bx0 = B[0], by0 = B[1], bx1 = B[2], by1 = B[3];
    float iw = fminf(ax1, bx1) - fmaxf(ax0, bx0);
    float ih = fminf(ay1, by1) - fmaxf(ay0, by0);
    bool pos = (iw > 0.f) && (ih > 0.f);
    float inter = pos ? iw * ih : 0.f;
    float a1 = (ax1 - ax0) * (ay1 - ay0);
    float a2 = (bx1 - bx0) * (by1 - by0);
    float den = a1 + a2 - inter;
    float r = pos ? inter / (den > 0.f ? den : 1.f) : 0.f;
    out[OUT_DTI + idx] = r;
}

// ---------------- kernel 4: vis-loss partials (closed-form gram) ----------------
__global__ void __launch_bounds__(256) vis_kernel(const float* __restrict__ vis,
                                                  const int* __restrict__ elen) {
    int a = blockIdx.x / NE, e = blockIdx.x % NE;
    int tid = threadIdx.x;
    int lane = tid & 31, w = tid >> 5;
    __shared__ float red[32];
    __shared__ float s_sim[NS];
    __shared__ int s_ind[NS];
    __shared__ float s_ssq[NS];
    __shared__ float s_f[NS];
    __shared__ float s_mn, s_mx;
    if (e >= elen[a]) {
        if (tid == 0) { g_vis_sum[blockIdx.x] = 0.f; g_vis_cnt[blockIdx.x] = 0; }
        return;
    }
    if (tid < NS) {
        int r = (a * NS + tid) * NCOL + (a * NE + e);
        s_sim[tid] = g_Dsim[r];
        s_ind[tid] = g_Dind[r];
    }
    __syncthreads();
    for (int s = w; s < NS; s += 8) {
        const float* u = vis + (size_t)((a * NS + s) * NB + s_ind[s]) * DD;
        const float4* u4 = (const float4*)u + lane * 4;
        float ss = 0.f;
#pragma unroll
        for (int q = 0; q < 4; q++) {
            float4 tt = u4[q];
            ss += tt.x * tt.x + tt.y * tt.y + tt.z * tt.z + tt.w * tt.w;
        }
        ss = warpSum(ss);
        if (lane == 0) s_ssq[s] = ss;
    }
    __syncthreads();
    if (tid == 0) {
        float mn = s_sim[0], mx = s_sim[0];
        for (int s = 1; s < NS; s++) { mn = fminf(mn, s_sim[s]); mx = fmaxf(mx, s_sim[s]); }
        s_mn = mn; s_mx = mx;
    }
    __syncthreads();
    if (tid < NS) {
        float nrm = sqrtf(s_ssq[tid]);
        float simn = (s_sim[tid] - s_mn) / (s_mx - s_mn + EPSF);
        s_f[tid] = simn / (nrm + EPSF);
    }
    __syncthreads();
    float a0 = 0.f, a1 = 0.f;
    int d0 = tid * 2;
#pragma unroll 4
    for (int s = 0; s < NS; s++) {
        const float* u = vis + (size_t)((a * NS + s) * NB + s_ind[s]) * DD;
        float f = s_f[s];
        a0 += u[d0] * f;
        a1 += u[d0 + 1] * f;
    }
    float tot = blockSum(a0 * a0 + a1 * a1, red);
    if (tid == 0) {
        float ssum = 0.f;
        for (int s = 0; s < NS; s++) ssum += s_f[s] * s_f[s] * s_ssq[s];
        g_vis_sum[blockIdx.x] = (float)(NS * (NS - 1)) - (tot - ssum);
        g_vis_cnt[blockIdx.x] = NS * (NS - 1);
    }
}

// ---------------- kernel 5a: Sf[a][s][a2] ----------------
__global__ void __launch_bounds__(1024) sf_kernel(const int* __restrict__ elen) {
    int a = blockIdx.x;
    int tid = threadIdx.x;
    __shared__ float smn[NCOL], smx[NCOL];
    if (tid < NCOL) {
        float mn = FLT_MAX, mx = -FLT_MAX;
        for (int s = 0; s < NS; s++) {
            float v = g_Dsim[(a * NS + s) * NCOL + tid];
            mn = fminf(mn, v); mx = fmaxf(mx, v);
        }
        smn[tid] = mn; smx[tid] = mx;
    }
    __syncthreads();
    int s = tid >> 4, a2 = tid & 15;
    const float* row = g_Dsim + (size_t)(a * NS + s) * NCOL;
    float acc = 0.f;
    for (int e = 0; e < NE; e++) {
        int c = a2 * NE + e;
        float v = row[c];
        acc += v * (v - smn[c]) / (smx[c] - smn[c] + EPSF);
    }
    int dv = elen[a2]; if (dv < 1) dv = 1;
    g_Sf[(a * NS + s) * NA + a2] = acc / (float)dv;
}

// ---------------- kernel 5b: margin loss ----------------
__global__ void __launch_bounds__(1024) loss_kernel(float* __restrict__ out) {
    int tid = threadIdx.x;
    int x = tid >> 6, s = tid & 63;
    __shared__ float red[32];
    float sfd_x = g_Sf[(x * NS + s) * NA + x];
    float t1 = 0.f, t2 = 0.f;
    for (int aa = 0; aa < NA; aa++) {
        float sf_a = g_Sf[(aa * NS + s) * NA + x];
        t1 += fmaxf(sf_a - sfd_x + DELTA_F, 0.f);
        float sf_x = g_Sf[(x * NS + s) * NA + aa];
        t2 += fmaxf(sf_x - sfd_x + DELTA_F, 0.f);
    }
    float fs = (t1 + t2) * (1.0f / (float)NA);
    float tot = blockSum(fs, red);
    if (tid == 0) {
        float vs = 0.f;
        long long vc = 0;
        for (int i = 0; i < NCOL; i++) { vs += g_vis_sum[i]; vc += g_vis_cnt[i]; }
        float vis_loss = vs / (float)(vc > 0 ? vc : 1);
        float margin = (tot / (float)(NA * NS) + 1.0f * vis_loss) * 10.0f;
        out[OUT_MARGIN] = margin;
    }
}

// ---------------- launch ----------------
extern "C" void kernel_launch(void* const* d_in, const int* in_sizes, int n_in,
                              void* d_out, int out_size) {
    const float* vis   = (const float*)d_in[0];
    const float* word  = (const float*)d_in[1];
    const float* boxes = (const float*)d_in[2];
    const float* dets  = (const float*)d_in[3];
    const int*   elen  = (const int*)d_in[4];
    float* out = (float*)d_out;

    cudaFuncSetAttribute(gemm_kernel, cudaFuncAttributeMaxDynamicSharedMemorySize, GEMM_SMEM);
    gemm_kernel<<<NROW / 128, 256, GEMM_SMEM>>>(vis, word);
    maxred_kernel<<<NGRP, NCOL>>>(elen, vis, word, out);
    iou_kernel<<<(N_DTI + 255) / 256, 256>>>(boxes, dets, out);
    vis_kernel<<<NCOL, 256>>>(vis, elen);
    sf_kernel<<<NA, 1024>>>(elen);
    loss_kernel<<<1, 1024>>>(out);
}